// round 10
// baseline (speedup 1.0000x reference)
#include <cuda_runtime.h>
#include <cuda_fp16.h>
#include <math.h>

#define SEQ 4096
#define DIM 1024

// ---------------------------------------------------------------------------
// Persistent scratch (__device__ globals; no-alloc rule)
// ---------------------------------------------------------------------------
__device__ __half g_Xh[SEQ * DIM];            // X cast to fp16
__device__ __half g_Wth[3 * DIM * DIM];       // W^T per slot: [n][k] fp16
__device__ __half g_QKVh[3 * SEQ * DIM];      // Q,K,V row-major [s][d] fp16
__device__ __half g_Vth[DIM * SEQ];           // V^T [d][s] fp16
__device__ float  g_S[(size_t)SEQ * SEQ];     // scores (unnormalized)
__device__ __half g_Ph[(size_t)SEQ * SEQ];    // exp(S - max) fp16
__device__ float  g_rowinv[SEQ];              // 1/rowsum for deferred norm

// ---------------------------------------------------------------------------
// PTX helpers
// ---------------------------------------------------------------------------
__device__ __forceinline__ unsigned smem_u32(const void* p) {
    unsigned a;
    asm("{ .reg .u64 t; cvta.to.shared.u64 t, %1; cvt.u32.u64 %0, t; }"
        : "=r"(a) : "l"(p));
    return a;
}

__device__ __forceinline__ void cp16(unsigned dst, const void* src) {
    asm volatile("cp.async.cg.shared.global [%0], [%1], 16;"
                 :: "r"(dst), "l"(src));
}
#define CP_COMMIT() asm volatile("cp.async.commit_group;" ::: "memory")
#define CP_WAIT1()  asm volatile("cp.async.wait_group 1;" ::: "memory")

__device__ __forceinline__ void ldm_x4(unsigned* r, unsigned addr) {
    asm volatile("ldmatrix.sync.aligned.m8n8.x4.shared.b16 {%0,%1,%2,%3}, [%4];"
                 : "=r"(r[0]), "=r"(r[1]), "=r"(r[2]), "=r"(r[3]) : "r"(addr));
}

__device__ __forceinline__ void mma4h(float* c, const unsigned* a, const unsigned* b) {
    asm volatile(
        "mma.sync.aligned.m16n8k16.row.col.f32.f16.f16.f32 "
        "{%0,%1,%2,%3}, {%4,%5,%6,%7}, {%8,%9}, {%0,%1,%2,%3};"
        : "+f"(c[0]), "+f"(c[1]), "+f"(c[2]), "+f"(c[3])
        : "r"(a[0]), "r"(a[1]), "r"(a[2]), "r"(a[3]), "r"(b[0]), "r"(b[1]));
}

// ---------------------------------------------------------------------------
// fp16 GEMM: C[M,N] = scale * A @ B^T (+bias)
// Tile 128x128xBK64, 8 warps (4m x 2n), warp tile 32x64, 2-stage cp.async.
// Inner loop software-pipelined: B jn-pair double buffer + A ks double
// buffer, so ldmatrix always overlaps MMA issue.
// PITCH=144B: conflict-free ldmatrix over 8-row groups.
// ---------------------------------------------------------------------------
#define PITCH       144
#define MAT_BYTES   (128 * PITCH)            // 18432
#define STAGE_BYTES (2 * MAT_BYTES)          // 36864
#define SMEM_BYTES  (2 * STAGE_BYTES)        // 73728
#define OFF_A 0
#define OFF_B MAT_BYTES

template <int EPI>
__global__ __launch_bounds__(256, 2) void h16_gemm(
    const __half* __restrict__ A, const __half* __restrict__ B,
    const float* __restrict__ bias0, const float* __restrict__ bias1,
    const float* __restrict__ bias2,
    const float* __restrict__ rowScale,
    float* __restrict__ Cf, __half* __restrict__ Ch,
    int M, int N, int K, float alpha, size_t bSlot, size_t cSlot)
{
    extern __shared__ char smem[];
    const unsigned sb = smem_u32(smem);
    const int tid = threadIdx.x;
    const int wid = tid >> 5;
    const int lane = tid & 31;
    const int bm = blockIdx.y * 128;
    const int bn = blockIdx.x * 128;
    const int z = blockIdx.z;

    B += (size_t)z * bSlot;

    const int warp_m = wid & 3;   // 0..3 -> 32 rows
    const int warp_n = wid >> 2;  // 0..1 -> 64 cols

    float acc[2][8][4];
    #pragma unroll
    for (int i = 0; i < 2; i++)
        #pragma unroll
        for (int j = 0; j < 8; j++)
            #pragma unroll
            for (int q = 0; q < 4; q++) acc[i][j][q] = 0.0f;

    // ldmatrix per-lane base offsets
    const unsigned aOff =
        (unsigned)((warp_m * 32 + (lane & 7) + ((lane >> 3) & 1) * 8) * PITCH
                   + (lane >> 4) * 16);
    const unsigned bOff =
        (unsigned)((warp_n * 64 + (lane & 7) + ((lane >> 4) & 1) * 8) * PITCH
                   + ((lane >> 3) & 1) * 16);

    // Loader: row = tid>>1 (0..127), 4+4 16B chunks per matrix row half.
    const int rr = tid >> 1;
    const int ch0 = (tid & 1) * 4;
    const unsigned dOff = (unsigned)(rr * PITCH + ch0 * 16);
    const __half* pa = A + (size_t)(bm + rr) * K + ch0 * 8;
    const __half* pb = B + (size_t)(bn + rr) * K + ch0 * 8;

    auto load_stage = [&](int stg, int kc) {
        const unsigned base = sb + stg * STAGE_BYTES;
        #pragma unroll
        for (int j = 0; j < 4; j++)
            cp16(base + OFF_A + dOff + j * 16, pa + kc + j * 8);
        #pragma unroll
        for (int j = 0; j < 4; j++)
            cp16(base + OFF_B + dOff + j * 16, pb + kc + j * 8);
    };

    const int nch = K >> 6;                   // BK = 64
    load_stage(0, 0);
    CP_COMMIT();

    for (int c = 0; c < nch; c++) {
        if (c + 1 < nch) load_stage((c + 1) & 1, (c + 1) << 6);
        CP_COMMIT();
        CP_WAIT1();
        __syncthreads();

        const unsigned stg = sb + (c & 1) * STAGE_BYTES;
        const unsigned aBase = stg + OFF_A + aOff;
        const unsigned bBase = stg + OFF_B + bOff;

        // Software-pipelined fragment flow:
        //   bufA[ks&1]  : A frags for current ks (2 ldm)
        //   bufB[0]     : B jn-pair 0 (jn 0,1) -> acc cols 0..3
        //   bufB[1]     : B jn-pair 1 (jn 2,3) -> acc cols 4..7
        unsigned bufA[2][8], bufB[2][8];

        // Preload ks=0: A + B pair0
        ldm_x4(bufA[0] + 0, aBase + 0 * (16 * PITCH));
        ldm_x4(bufA[0] + 4, aBase + 1 * (16 * PITCH));
        ldm_x4(bufB[0] + 0, bBase + 0 * (16 * PITCH));
        ldm_x4(bufB[0] + 4, bBase + 1 * (16 * PITCH));

        #pragma unroll
        for (int ks = 0; ks < 4; ks++) {
            const unsigned* aa = bufA[ks & 1];
            const unsigned kk = (unsigned)(ks * 32);

            // load B pair1 of this ks while pair0 MMAs issue
            ldm_x4(bufB[1] + 0, bBase + 2 * (16 * PITCH) + kk);
            ldm_x4(bufB[1] + 4, bBase + 3 * (16 * PITCH) + kk);

            #pragma unroll
            for (int im = 0; im < 2; im++) {
                mma4h(acc[im][0], aa + im * 4, bufB[0] + 0);
                mma4h(acc[im][1], aa + im * 4, bufB[0] + 2);
                mma4h(acc[im][2], aa + im * 4, bufB[0] + 4);
                mma4h(acc[im][3], aa + im * 4, bufB[0] + 6);
            }

            // prefetch next-ks A and B pair0 while pair1 MMAs issue
            if (ks < 3) {
                const unsigned kn = (unsigned)((ks + 1) * 32);
                ldm_x4(bufA[(ks + 1) & 1] + 0, aBase + 0 * (16 * PITCH) + kn);
                ldm_x4(bufA[(ks + 1) & 1] + 4, aBase + 1 * (16 * PITCH) + kn);
                ldm_x4(bufB[0] + 0, bBase + 0 * (16 * PITCH) + kn);
                ldm_x4(bufB[0] + 4, bBase + 1 * (16 * PITCH) + kn);
            }

            #pragma unroll
            for (int im = 0; im < 2; im++) {
                mma4h(acc[im][4], aa + im * 4, bufB[1] + 0);
                mma4h(acc[im][5], aa + im * 4, bufB[1] + 2);
                mma4h(acc[im][6], aa + im * 4, bufB[1] + 4);
                mma4h(acc[im][7], aa + im * 4, bufB[1] + 6);
            }
        }
        __syncthreads();
    }

    // ---- Epilogue ----
    const int r0 = bm + warp_m * 32 + (lane >> 2);
    const int c0 = bn + warp_n * 64 + (lane & 3) * 2;

    if (EPI == 0) {
        Cf += (size_t)z * cSlot;
        #pragma unroll
        for (int im = 0; im < 2; im++)
            #pragma unroll
            for (int j = 0; j < 8; j++) {
                const int row = r0 + im * 16;
                const int col = c0 + j * 8;
                const float s0 = rowScale ? rowScale[row] : alpha;
                const float s1 = rowScale ? rowScale[row + 8] : alpha;
                float2 v0 = make_float2(s0 * acc[im][j][0], s0 * acc[im][j][1]);
                float2 v1 = make_float2(s1 * acc[im][j][2], s1 * acc[im][j][3]);
                *reinterpret_cast<float2*>(&Cf[(size_t)row * N + col]) = v0;
                *reinterpret_cast<float2*>(&Cf[(size_t)(row + 8) * N + col]) = v1;
            }
    } else {
        const float* bias = (z == 0) ? bias0 : (z == 1) ? bias1 : bias2;
        Ch += (size_t)z * cSlot;
        #pragma unroll
        for (int im = 0; im < 2; im++)
            #pragma unroll
            for (int j = 0; j < 8; j++) {
                const int row = r0 + im * 16;
                const int col = c0 + j * 8;
                const float b0 = bias[col], b1 = bias[col + 1];
                #pragma unroll
                for (int h = 0; h < 2; h++) {
                    const int rw = row + h * 8;
                    __half2 hv;
                    hv.x = __float2half_rn(acc[im][j][h * 2 + 0] + b0);
                    hv.y = __float2half_rn(acc[im][j][h * 2 + 1] + b1);
                    *reinterpret_cast<__half2*>(&Ch[(size_t)rw * N + col]) = hv;
                }
            }
    }
}

// ---------------------------------------------------------------------------
// X fp32 -> fp16
// ---------------------------------------------------------------------------
__global__ __launch_bounds__(256) void xcast(
    const float* __restrict__ X, __half* __restrict__ Xh)
{
    const size_t i = ((size_t)blockIdx.x * 256 + threadIdx.x) * 4;
    float4 v = *reinterpret_cast<const float4*>(&X[i]);
    __half2 h0, h1;
    h0.x = __float2half_rn(v.x); h0.y = __float2half_rn(v.y);
    h1.x = __float2half_rn(v.z); h1.y = __float2half_rn(v.w);
    *reinterpret_cast<__half2*>(&Xh[i]) = h0;
    *reinterpret_cast<__half2*>(&Xh[i + 2]) = h1;
}

// ---------------------------------------------------------------------------
// W [K][N] fp32 -> W^T [n][k] fp16, slot z
// ---------------------------------------------------------------------------
__global__ void wtrans(const float* __restrict__ Wq, const float* __restrict__ Wk,
                       const float* __restrict__ Wv, __half* __restrict__ Th)
{
    __shared__ float tile[32][33];
    const int z = blockIdx.z;
    const float* W = (z == 0) ? Wq : (z == 1) ? Wk : Wv;
    const int n0 = blockIdx.x * 32, k0 = blockIdx.y * 32;
    const int tx = threadIdx.x, ty = threadIdx.y;
    #pragma unroll
    for (int i = 0; i < 32; i += 8)
        tile[ty + i][tx] = W[(size_t)(k0 + ty + i) * DIM + n0 + tx];
    __syncthreads();
    const size_t base = (size_t)z * DIM * DIM;
    #pragma unroll
    for (int i = 0; i < 32; i += 8)
        Th[base + (size_t)(n0 + ty + i) * DIM + k0 + tx] =
            __float2half_rn(tile[tx][ty + i]);
}

// ---------------------------------------------------------------------------
// V fp16 [SEQ][DIM] -> V^T fp16 [DIM][SEQ]
// ---------------------------------------------------------------------------
__global__ void vtrans(const __half* __restrict__ V, __half* __restrict__ Vt)
{
    __shared__ __half t[32][33];
    const int d0 = blockIdx.x * 32, s0 = blockIdx.y * 32;
    const int tx = threadIdx.x, ty = threadIdx.y;
    #pragma unroll
    for (int i = 0; i < 32; i += 8)
        t[ty + i][tx] = V[(size_t)(s0 + ty + i) * DIM + d0 + tx];
    __syncthreads();
    #pragma unroll
    for (int i = 0; i < 32; i += 8)
        Vt[(size_t)(d0 + ty + i) * SEQ + s0 + tx] = t[tx][ty + i];
}

// ---------------------------------------------------------------------------
// Row softmax (deferred normalization): Ph = fp16(exp(S - max)),
// rowinv = 1/rowsum (applied in PV epilogue). One block per row.
// ---------------------------------------------------------------------------
__global__ __launch_bounds__(256) void softmax_h(
    const float* __restrict__ S, __half* __restrict__ Ph,
    float* __restrict__ rowinv)
{
    const size_t rowoff = (size_t)blockIdx.x * SEQ;
    const float* p = S + rowoff;
    __shared__ float red[256];
    const int tid = threadIdx.x;

    float m = -INFINITY;
    #pragma unroll
    for (int t = 0; t < 4; t++) {
        float4 v = *reinterpret_cast<const float4*>(&p[tid * 4 + t * 1024]);
        m = fmaxf(m, fmaxf(fmaxf(v.x, v.y), fmaxf(v.z, v.w)));
    }
    red[tid] = m;
    __syncthreads();
    for (int s = 128; s > 0; s >>= 1) {
        if (tid < s) red[tid] = fmaxf(red[tid], red[tid + s]);
        __syncthreads();
    }
    m = red[0];
    __syncthreads();

    float sum = 0.0f;
    #pragma unroll
    for (int t = 0; t < 4; t++) {
        const int i = tid * 4 + t * 1024;
        float4 v = *reinterpret_cast<const float4*>(&p[i]);
        v.x = expf(v.x - m); v.y = expf(v.y - m);
        v.z = expf(v.z - m); v.w = expf(v.w - m);
        sum += v.x + v.y + v.z + v.w;
        __half2 h0, h1;
        h0.x = __float2half_rn(v.x); h0.y = __float2half_rn(v.y);
        h1.x = __float2half_rn(v.z); h1.y = __float2half_rn(v.w);
        *reinterpret_cast<__half2*>(&Ph[rowoff + i]) = h0;
        *reinterpret_cast<__half2*>(&Ph[rowoff + i + 2]) = h1;
    }
    red[tid] = sum;
    __syncthreads();
    for (int s = 128; s > 0; s >>= 1) {
        if (tid < s) red[tid] += red[tid + s];
        __syncthreads();
    }
    if (tid == 0) rowinv[blockIdx.x] = 1.0f / red[0];
}

// ---------------------------------------------------------------------------
// Launch — ordered so the ncu capture (launch #4) hits the big QK^T GEMM.
// ---------------------------------------------------------------------------
extern "C" void kernel_launch(void* const* d_in, const int* in_sizes, int n_in,
                              void* d_out, int out_size)
{
    const float* X  = (const float*)d_in[0];
    const float* Wq = (const float*)d_in[1];
    const float* bq = (const float*)d_in[2];
    const float* Wk = (const float*)d_in[3];
    const float* bk = (const float*)d_in[4];
    const float* Wv = (const float*)d_in[5];
    const float* bv = (const float*)d_in[6];
    float* out = (float*)d_out;

    __half *Xh, *Wth, *QKVh, *Vth, *Ph;
    float *S, *rowinv;
    cudaGetSymbolAddress((void**)&Xh, g_Xh);
    cudaGetSymbolAddress((void**)&Wth, g_Wth);
    cudaGetSymbolAddress((void**)&QKVh, g_QKVh);
    cudaGetSymbolAddress((void**)&Vth, g_Vth);
    cudaGetSymbolAddress((void**)&S, g_S);
    cudaGetSymbolAddress((void**)&Ph, g_Ph);
    cudaGetSymbolAddress((void**)&rowinv, g_rowinv);

    cudaFuncSetAttribute(h16_gemm<0>, cudaFuncAttributeMaxDynamicSharedMemorySize, SMEM_BYTES);
    cudaFuncSetAttribute(h16_gemm<1>, cudaFuncAttributeMaxDynamicSharedMemorySize, SMEM_BYTES);

    // 1) X -> fp16
    xcast<<<SEQ * DIM / 1024, 256>>>(X, Xh);
    // 2) W -> W^T fp16 (3 slots)
    wtrans<<<dim3(DIM / 32, DIM / 32, 3), dim3(32, 8)>>>(Wq, Wk, Wv, Wth);
    // 3) QKV projections (fused over z) + bias -> fp16
    h16_gemm<1><<<dim3(DIM / 128, SEQ / 128, 3), 256, SMEM_BYTES>>>(
        Xh, Wth, bq, bk, bv, nullptr,
        nullptr, QKVh,
        SEQ, DIM, DIM, 1.0f, (size_t)DIM * DIM, (size_t)SEQ * DIM);
    // 4) S = (Q @ K^T) / 32   <-- ncu capture target (launch #4)
    h16_gemm<0><<<dim3(SEQ / 128, SEQ / 128, 1), 256, SMEM_BYTES>>>(
        QKVh, QKVh + (size_t)SEQ * DIM,
        nullptr, nullptr, nullptr, nullptr,
        S, nullptr,
        SEQ, SEQ, DIM, 1.0f / 32.0f, 0, 0);
    // 5) V^T fp16
    vtrans<<<dim3(DIM / 32, SEQ / 32), dim3(32, 8)>>>(
        QKVh + 2 * (size_t)SEQ * DIM, Vth);
    // 6) softmax (deferred norm) -> P fp16 + rowinv
    softmax_h<<<SEQ, 256>>>(S, Ph, rowinv);
    // 7) out = (P @ V^T) * rowinv[row]
    h16_gemm<0><<<dim3(DIM / 128, SEQ / 128, 1), 256, SMEM_BYTES>>>(
        Ph, Vth,
        nullptr, nullptr, nullptr, rowinv,
        out, nullptr,
        SEQ, DIM, SEQ, 1.0f, 0, 0);
}

// round 13
// speedup vs baseline: 1.0237x; 1.0237x over previous
#include <cuda_runtime.h>
#include <cuda_fp16.h>
#include <math.h>

#define SEQ 4096
#define DIM 1024

// ---------------------------------------------------------------------------
// Persistent scratch (__device__ globals; no-alloc rule)
// ---------------------------------------------------------------------------
__device__ __half g_Xh[SEQ * DIM];            // X cast to fp16
__device__ __half g_Wth[3 * DIM * DIM];       // W^T per slot: [n][k] fp16
__device__ __half g_QKVh[3 * SEQ * DIM];      // Q,K,V row-major [s][d] fp16
__device__ __half g_Vth[DIM * SEQ];           // V^T [d][s] fp16
__device__ float  g_S[(size_t)SEQ * SEQ];     // scores (unnormalized)
__device__ __half g_Ph[(size_t)SEQ * SEQ];    // exp(S - max) fp16
__device__ float  g_rowinv[SEQ];              // 1/rowsum for deferred norm

// ---------------------------------------------------------------------------
// PTX helpers
// ---------------------------------------------------------------------------
__device__ __forceinline__ unsigned smem_u32(const void* p) {
    unsigned a;
    asm("{ .reg .u64 t; cvta.to.shared.u64 t, %1; cvt.u32.u64 %0, t; }"
        : "=r"(a) : "l"(p));
    return a;
}

__device__ __forceinline__ void cp16(unsigned dst, const void* src) {
    asm volatile("cp.async.cg.shared.global [%0], [%1], 16;"
                 :: "r"(dst), "l"(src));
}
#define CP_COMMIT() asm volatile("cp.async.commit_group;" ::: "memory")
#define CP_WAIT2()  asm volatile("cp.async.wait_group 2;" ::: "memory")

__device__ __forceinline__ void ldm_x4(unsigned* r, unsigned addr) {
    asm volatile("ldmatrix.sync.aligned.m8n8.x4.shared.b16 {%0,%1,%2,%3}, [%4];"
                 : "=r"(r[0]), "=r"(r[1]), "=r"(r[2]), "=r"(r[3]) : "r"(addr));
}

__device__ __forceinline__ void mma4h(float* c, const unsigned* a, const unsigned* b) {
    asm volatile(
        "mma.sync.aligned.m16n8k16.row.col.f32.f16.f16.f32 "
        "{%0,%1,%2,%3}, {%4,%5,%6,%7}, {%8,%9}, {%0,%1,%2,%3};"
        : "+f"(c[0]), "+f"(c[1]), "+f"(c[2]), "+f"(c[3])
        : "r"(a[0]), "r"(a[1]), "r"(a[2]), "r"(a[3]), "r"(b[0]), "r"(b[1]));
}

// ---------------------------------------------------------------------------
// fp16 GEMM: C[M,N] = scale * A @ B^T (+bias)
// Tile 256x128xBK64, 16 warps (8m x 2n), warp tile 32x64, 3-stage cp.async,
// ONE CTA per SM (arithmetic intensity 42 MAC/B vs 16 at 128x128: per-chunk
// smem fill 48KB for 2M MACs -> feed time ~matches tensor time).
// PITCH=144B: conflict-free ldmatrix over 8-row groups.
// ---------------------------------------------------------------------------
#define PITCH       144
#define A_MAT       (256 * PITCH)            // 36864
#define B_MAT       (128 * PITCH)            // 18432
#define STAGE_BYTES (A_MAT + B_MAT)          // 55296
#define NSTAGE      3
#define SMEM_BYTES  (NSTAGE * STAGE_BYTES)   // 165888 (<227KB cap, opt-in set)
#define OFF_A 0
#define OFF_B A_MAT

template <int EPI>
__global__ __launch_bounds__(512, 1) void h16_gemm(
    const __half* __restrict__ A, const __half* __restrict__ B,
    const float* __restrict__ bias0, const float* __restrict__ bias1,
    const float* __restrict__ bias2,
    const float* __restrict__ rowScale,
    float* __restrict__ Cf, __half* __restrict__ Ch,
    int M, int N, int K, float alpha, size_t bSlot, size_t cSlot)
{
    extern __shared__ char smem[];
    const unsigned sb = smem_u32(smem);
    const int tid = threadIdx.x;
    const int wid = tid >> 5;
    const int lane = tid & 31;
    const int bm = blockIdx.y * 256;
    const int bn = blockIdx.x * 128;
    const int z = blockIdx.z;

    B += (size_t)z * bSlot;

    const int warp_m = wid & 7;   // 0..7 -> 32 rows each
    const int warp_n = wid >> 3;  // 0..1 -> 64 cols each

    float acc[2][8][4];
    #pragma unroll
    for (int i = 0; i < 2; i++)
        #pragma unroll
        for (int j = 0; j < 8; j++)
            #pragma unroll
            for (int q = 0; q < 4; q++) acc[i][j][q] = 0.0f;

    // ldmatrix per-lane base offsets
    const unsigned aOff =
        (unsigned)((warp_m * 32 + (lane & 7) + ((lane >> 3) & 1) * 8) * PITCH
                   + (lane >> 4) * 16);
    const unsigned bOff =
        (unsigned)((warp_n * 64 + (lane & 7) + ((lane >> 4) & 1) * 8) * PITCH
                   + ((lane >> 3) & 1) * 16);

    // Loader: A 256 rows x 8 chunks (2 thr/row, 4 chunks each);
    //         B 128 rows x 8 chunks (4 thr/row, 2 chunks each). 6 cp16/thread.
    const int rA = tid >> 1;                  // 0..255
    const int cA = (tid & 1) * 4;             // 0 or 4
    const int rB = tid >> 2;                  // 0..127
    const int cB = (tid & 3) * 2;             // 0,2,4,6
    const unsigned dA = (unsigned)(rA * PITCH + cA * 16);
    const unsigned dB = (unsigned)(rB * PITCH + cB * 16);
    const __half* pa = A + (size_t)(bm + rA) * K + cA * 8;
    const __half* pb = B + (size_t)(bn + rB) * K + cB * 8;

    auto load_stage = [&](int stg, int kc) {
        const unsigned base = sb + stg * STAGE_BYTES;
        #pragma unroll
        for (int j = 0; j < 4; j++)
            cp16(base + OFF_A + dA + j * 16, pa + kc + j * 8);
        #pragma unroll
        for (int j = 0; j < 2; j++)
            cp16(base + OFF_B + dB + j * 16, pb + kc + j * 8);
    };

    const int nch = K >> 6;                   // BK = 64
    load_stage(0, 0);
    CP_COMMIT();
    if (nch > 1) load_stage(1, 64);
    CP_COMMIT();

    int stg = 0;
    for (int c = 0; c < nch; c++) {
        if (c + 2 < nch) { load_stage((c + 2) % NSTAGE, (c + 2) << 6); }
        CP_COMMIT();
        CP_WAIT2();
        __syncthreads();

        const unsigned aBase = sb + stg * STAGE_BYTES + OFF_A + aOff;
        const unsigned bBase = sb + stg * STAGE_BYTES + OFF_B + bOff;

        #pragma unroll
        for (int ks = 0; ks < 4; ks++) {
            const unsigned kk = (unsigned)(ks * 32);
            unsigned aa[2][4], bb[4][4];
            ldm_x4(aa[0], aBase + 0 * (16 * PITCH) + kk);
            ldm_x4(aa[1], aBase + 1 * (16 * PITCH) + kk);
            #pragma unroll
            for (int jn = 0; jn < 4; jn++)
                ldm_x4(bb[jn], bBase + jn * (16 * PITCH) + kk);
            #pragma unroll
            for (int im = 0; im < 2; im++)
                #pragma unroll
                for (int jn = 0; jn < 4; jn++) {
                    mma4h(acc[im][2 * jn],     aa[im], bb[jn] + 0);
                    mma4h(acc[im][2 * jn + 1], aa[im], bb[jn] + 2);
                }
        }
        __syncthreads();
        stg = (stg + 1 == NSTAGE) ? 0 : stg + 1;
    }

    // ---- Epilogue ----
    const int r0 = bm + warp_m * 32 + (lane >> 2);
    const int c0 = bn + warp_n * 64 + (lane & 3) * 2;

    if (EPI == 0) {
        Cf += (size_t)z * cSlot;
        #pragma unroll
        for (int im = 0; im < 2; im++)
            #pragma unroll
            for (int j = 0; j < 8; j++) {
                const int row = r0 + im * 16;
                const int col = c0 + j * 8;
                const float s0 = rowScale ? rowScale[row] : alpha;
                const float s1 = rowScale ? rowScale[row + 8] : alpha;
                float2 v0 = make_float2(s0 * acc[im][j][0], s0 * acc[im][j][1]);
                float2 v1 = make_float2(s1 * acc[im][j][2], s1 * acc[im][j][3]);
                *reinterpret_cast<float2*>(&Cf[(size_t)row * N + col]) = v0;
                *reinterpret_cast<float2*>(&Cf[(size_t)(row + 8) * N + col]) = v1;
            }
    } else {
        const float* bias = (z == 0) ? bias0 : (z == 1) ? bias1 : bias2;
        Ch += (size_t)z * cSlot;
        #pragma unroll
        for (int im = 0; im < 2; im++)
            #pragma unroll
            for (int j = 0; j < 8; j++) {
                const int row = r0 + im * 16;
                const int col = c0 + j * 8;
                const float b0 = bias[col], b1 = bias[col + 1];
                #pragma unroll
                for (int h = 0; h < 2; h++) {
                    const int rw = row + h * 8;
                    __half2 hv;
                    hv.x = __float2half_rn(acc[im][j][h * 2 + 0] + b0);
                    hv.y = __float2half_rn(acc[im][j][h * 2 + 1] + b1);
                    *reinterpret_cast<__half2*>(&Ch[(size_t)rw * N + col]) = hv;
                }
            }
    }
}

// ---------------------------------------------------------------------------
// X fp32 -> fp16
// ---------------------------------------------------------------------------
__global__ __launch_bounds__(256) void xcast(
    const float* __restrict__ X, __half* __restrict__ Xh)
{
    const size_t i = ((size_t)blockIdx.x * 256 + threadIdx.x) * 4;
    float4 v = *reinterpret_cast<const float4*>(&X[i]);
    __half2 h0, h1;
    h0.x = __float2half_rn(v.x); h0.y = __float2half_rn(v.y);
    h1.x = __float2half_rn(v.z); h1.y = __float2half_rn(v.w);
    *reinterpret_cast<__half2*>(&Xh[i]) = h0;
    *reinterpret_cast<__half2*>(&Xh[i + 2]) = h1;
}

// ---------------------------------------------------------------------------
// W [K][N] fp32 -> W^T [n][k] fp16, slot z
// ---------------------------------------------------------------------------
__global__ void wtrans(const float* __restrict__ Wq, const float* __restrict__ Wk,
                       const float* __restrict__ Wv, __half* __restrict__ Th)
{
    __shared__ float tile[32][33];
    const int z = blockIdx.z;
    const float* W = (z == 0) ? Wq : (z == 1) ? Wk : Wv;
    const int n0 = blockIdx.x * 32, k0 = blockIdx.y * 32;
    const int tx = threadIdx.x, ty = threadIdx.y;
    #pragma unroll
    for (int i = 0; i < 32; i += 8)
        tile[ty + i][tx] = W[(size_t)(k0 + ty + i) * DIM + n0 + tx];
    __syncthreads();
    const size_t base = (size_t)z * DIM * DIM;
    #pragma unroll
    for (int i = 0; i < 32; i += 8)
        Th[base + (size_t)(n0 + ty + i) * DIM + k0 + tx] =
            __float2half_rn(tile[tx][ty + i]);
}

// ---------------------------------------------------------------------------
// V fp16 [SEQ][DIM] -> V^T fp16 [DIM][SEQ]
// ---------------------------------------------------------------------------
__global__ void vtrans(const __half* __restrict__ V, __half* __restrict__ Vt)
{
    __shared__ __half t[32][33];
    const int d0 = blockIdx.x * 32, s0 = blockIdx.y * 32;
    const int tx = threadIdx.x, ty = threadIdx.y;
    #pragma unroll
    for (int i = 0; i < 32; i += 8)
        t[ty + i][tx] = V[(size_t)(s0 + ty + i) * DIM + d0 + tx];
    __syncthreads();
    #pragma unroll
    for (int i = 0; i < 32; i += 8)
        Vt[(size_t)(d0 + ty + i) * SEQ + s0 + tx] = t[tx][ty + i];
}

// ---------------------------------------------------------------------------
// Row softmax (deferred normalization): Ph = fp16(exp(S - max)),
// rowinv = 1/rowsum (applied in PV epilogue). One block per row.
// ---------------------------------------------------------------------------
__global__ __launch_bounds__(256) void softmax_h(
    const float* __restrict__ S, __half* __restrict__ Ph,
    float* __restrict__ rowinv)
{
    const size_t rowoff = (size_t)blockIdx.x * SEQ;
    const float* p = S + rowoff;
    __shared__ float red[256];
    const int tid = threadIdx.x;

    float m = -INFINITY;
    #pragma unroll
    for (int t = 0; t < 4; t++) {
        float4 v = *reinterpret_cast<const float4*>(&p[tid * 4 + t * 1024]);
        m = fmaxf(m, fmaxf(fmaxf(v.x, v.y), fmaxf(v.z, v.w)));
    }
    red[tid] = m;
    __syncthreads();
    for (int s = 128; s > 0; s >>= 1) {
        if (tid < s) red[tid] = fmaxf(red[tid], red[tid + s]);
        __syncthreads();
    }
    m = red[0];
    __syncthreads();

    float sum = 0.0f;
    #pragma unroll
    for (int t = 0; t < 4; t++) {
        const int i = tid * 4 + t * 1024;
        float4 v = *reinterpret_cast<const float4*>(&p[i]);
        v.x = expf(v.x - m); v.y = expf(v.y - m);
        v.z = expf(v.z - m); v.w = expf(v.w - m);
        sum += v.x + v.y + v.z + v.w;
        __half2 h0, h1;
        h0.x = __float2half_rn(v.x); h0.y = __float2half_rn(v.y);
        h1.x = __float2half_rn(v.z); h1.y = __float2half_rn(v.w);
        *reinterpret_cast<__half2*>(&Ph[rowoff + i]) = h0;
        *reinterpret_cast<__half2*>(&Ph[rowoff + i + 2]) = h1;
    }
    red[tid] = sum;
    __syncthreads();
    for (int s = 128; s > 0; s >>= 1) {
        if (tid < s) red[tid] += red[tid + s];
        __syncthreads();
    }
    if (tid == 0) rowinv[blockIdx.x] = 1.0f / red[0];
}

// ---------------------------------------------------------------------------
// Launch — ordered so the ncu capture (launch #4) hits the big QK^T GEMM.
// ---------------------------------------------------------------------------
extern "C" void kernel_launch(void* const* d_in, const int* in_sizes, int n_in,
                              void* d_out, int out_size)
{
    const float* X  = (const float*)d_in[0];
    const float* Wq = (const float*)d_in[1];
    const float* bq = (const float*)d_in[2];
    const float* Wk = (const float*)d_in[3];
    const float* bk = (const float*)d_in[4];
    const float* Wv = (const float*)d_in[5];
    const float* bv = (const float*)d_in[6];
    float* out = (float*)d_out;

    __half *Xh, *Wth, *QKVh, *Vth, *Ph;
    float *S, *rowinv;
    cudaGetSymbolAddress((void**)&Xh, g_Xh);
    cudaGetSymbolAddress((void**)&Wth, g_Wth);
    cudaGetSymbolAddress((void**)&QKVh, g_QKVh);
    cudaGetSymbolAddress((void**)&Vth, g_Vth);
    cudaGetSymbolAddress((void**)&S, g_S);
    cudaGetSymbolAddress((void**)&Ph, g_Ph);
    cudaGetSymbolAddress((void**)&rowinv, g_rowinv);

    cudaFuncSetAttribute(h16_gemm<0>, cudaFuncAttributeMaxDynamicSharedMemorySize, SMEM_BYTES);
    cudaFuncSetAttribute(h16_gemm<1>, cudaFuncAttributeMaxDynamicSharedMemorySize, SMEM_BYTES);

    // 1) X -> fp16
    xcast<<<SEQ * DIM / 1024, 256>>>(X, Xh);
    // 2) W -> W^T fp16 (3 slots)
    wtrans<<<dim3(DIM / 32, DIM / 32, 3), dim3(32, 8)>>>(Wq, Wk, Wv, Wth);
    // 3) QKV projections (fused over z) + bias -> fp16
    h16_gemm<1><<<dim3(DIM / 128, SEQ / 256, 3), 512, SMEM_BYTES>>>(
        Xh, Wth, bq, bk, bv, nullptr,
        nullptr, QKVh,
        SEQ, DIM, DIM, 1.0f, (size_t)DIM * DIM, (size_t)SEQ * DIM);
    // 4) S = (Q @ K^T) / 32   <-- ncu capture target (launch #4)
    h16_gemm<0><<<dim3(SEQ / 128, SEQ / 256, 1), 512, SMEM_BYTES>>>(
        QKVh, QKVh + (size_t)SEQ * DIM,
        nullptr, nullptr, nullptr, nullptr,
        S, nullptr,
        SEQ, SEQ, DIM, 1.0f / 32.0f, 0, 0);
    // 5) V^T fp16
    vtrans<<<dim3(DIM / 32, SEQ / 32), dim3(32, 8)>>>(
        QKVh + 2 * (size_t)SEQ * DIM, Vth);
    // 6) softmax (deferred norm) -> P fp16 + rowinv
    softmax_h<<<SEQ, 256>>>(S, Ph, rowinv);
    // 7) out = (P @ V^T) * rowinv[row]
    h16_gemm<0><<<dim3(DIM / 128, SEQ / 256, 1), 512, SMEM_BYTES>>>(
        Ph, Vth,
        nullptr, nullptr, nullptr, rowinv,
        out, nullptr,
        SEQ, DIM, SEQ, 1.0f, 0, 0);
}

// round 16
// speedup vs baseline: 1.0421x; 1.0180x over previous
#include <cuda_runtime.h>
#include <cuda_fp16.h>
#include <math.h>

#define SEQ 4096
#define DIM 1024

// ---------------------------------------------------------------------------
// Persistent scratch (__device__ globals; no-alloc rule)
// ---------------------------------------------------------------------------
__device__ __half g_Xh[SEQ * DIM];            // X cast to fp16
__device__ __half g_Wth[3 * DIM * DIM];       // W^T per slot: [n][k] fp16
__device__ __half g_QKVh[3 * SEQ * DIM];      // Q,K,V row-major [s][d] fp16
__device__ __half g_Vth[DIM * SEQ];           // V^T [d][s] fp16
__device__ float  g_S[(size_t)SEQ * SEQ];     // scores (unnormalized)
__device__ __half g_Ph[(size_t)SEQ * SEQ];    // exp(S - max) fp16
__device__ float  g_rowinv[SEQ];              // 1/rowsum for deferred norm

// ---------------------------------------------------------------------------
// PTX helpers
// ---------------------------------------------------------------------------
__device__ __forceinline__ unsigned smem_u32(const void* p) {
    unsigned a;
    asm("{ .reg .u64 t; cvta.to.shared.u64 t, %1; cvt.u32.u64 %0, t; }"
        : "=r"(a) : "l"(p));
    return a;
}

__device__ __forceinline__ void cp16(unsigned dst, const void* src) {
    asm volatile("cp.async.cg.shared.global [%0], [%1], 16;"
                 :: "r"(dst), "l"(src));
}
#define CP_COMMIT() asm volatile("cp.async.commit_group;" ::: "memory")
#define CP_WAIT1()  asm volatile("cp.async.wait_group 1;" ::: "memory")

__device__ __forceinline__ void ldm_x4(unsigned* r, unsigned addr) {
    asm volatile("ldmatrix.sync.aligned.m8n8.x4.shared.b16 {%0,%1,%2,%3}, [%4];"
                 : "=r"(r[0]), "=r"(r[1]), "=r"(r[2]), "=r"(r[3]) : "r"(addr));
}

__device__ __forceinline__ void mma4h(float* c, const unsigned* a, const unsigned* b) {
    asm volatile(
        "mma.sync.aligned.m16n8k16.row.col.f32.f16.f16.f32 "
        "{%0,%1,%2,%3}, {%4,%5,%6,%7}, {%8,%9}, {%0,%1,%2,%3};"
        : "+f"(c[0]), "+f"(c[1]), "+f"(c[2]), "+f"(c[3])
        : "r"(a[0]), "r"(a[1]), "r"(a[2]), "r"(a[3]), "r"(b[0]), "r"(b[1]));
}

// ---------------------------------------------------------------------------
// fp16 GEMM: C[M,N] = scale * A @ B^T (+bias)
// Tile 128x128xBK64, 8 warps (4m x 2n), warp tile 32x64, 2 CTAs/SM.
// 3-stage cp.async with ONE __syncthreads per chunk:
//   WAIT -> bar -> issue loads for chunk c+2 -> MMA chunk c.
// Stage (c+2)%3 was last read in chunk c-1; the bar orders those reads
// before the new writes. 2 chunks always in flight.
// PITCH=144B: conflict-free ldmatrix reads and cp.async writes.
// ---------------------------------------------------------------------------
#define PITCH       144
#define MAT_BYTES   (128 * PITCH)            // 18432
#define STAGE_BYTES (2 * MAT_BYTES)          // 36864
#define NSTAGE      3
#define SMEM_BYTES  (NSTAGE * STAGE_BYTES)   // 110592 (x2 CTA = 221KB <= 228KB)
#define OFF_A 0
#define OFF_B MAT_BYTES

template <int EPI>
__global__ __launch_bounds__(256, 2) void h16_gemm(
    const __half* __restrict__ A, const __half* __restrict__ B,
    const float* __restrict__ bias0, const float* __restrict__ bias1,
    const float* __restrict__ bias2,
    const float* __restrict__ rowScale,
    float* __restrict__ Cf, __half* __restrict__ Ch,
    int M, int N, int K, float alpha, size_t bSlot, size_t cSlot)
{
    extern __shared__ char smem[];
    const unsigned sb = smem_u32(smem);
    const int tid = threadIdx.x;
    const int wid = tid >> 5;
    const int lane = tid & 31;
    const int bm = blockIdx.y * 128;
    const int bn = blockIdx.x * 128;
    const int z = blockIdx.z;

    B += (size_t)z * bSlot;

    const int warp_m = wid & 3;   // 0..3 -> 32 rows
    const int warp_n = wid >> 2;  // 0..1 -> 64 cols

    float acc[2][8][4];
    #pragma unroll
    for (int i = 0; i < 2; i++)
        #pragma unroll
        for (int j = 0; j < 8; j++)
            #pragma unroll
            for (int q = 0; q < 4; q++) acc[i][j][q] = 0.0f;

    // ldmatrix per-lane base offsets
    const unsigned aOff =
        (unsigned)((warp_m * 32 + (lane & 7) + ((lane >> 3) & 1) * 8) * PITCH
                   + (lane >> 4) * 16);
    const unsigned bOff =
        (unsigned)((warp_n * 64 + (lane & 7) + ((lane >> 4) & 1) * 8) * PITCH
                   + ((lane >> 3) & 1) * 16);

    // Loader: row = tid>>1 (0..127), 4 chunks of 16B per matrix half-row.
    const int rr = tid >> 1;
    const int ch0 = (tid & 1) * 4;
    const unsigned dOff = (unsigned)(rr * PITCH + ch0 * 16);
    const __half* pa = A + (size_t)(bm + rr) * K + ch0 * 8;
    const __half* pb = B + (size_t)(bn + rr) * K + ch0 * 8;

    auto load_stage = [&](int stg, int kc) {
        const unsigned base = sb + stg * STAGE_BYTES;
        #pragma unroll
        for (int j = 0; j < 4; j++)
            cp16(base + OFF_A + dOff + j * 16, pa + kc + j * 8);
        #pragma unroll
        for (int j = 0; j < 4; j++)
            cp16(base + OFF_B + dOff + j * 16, pb + kc + j * 8);
    };

    const int nch = K >> 6;                   // BK = 64; nch >= 16
    load_stage(0, 0);
    CP_COMMIT();
    load_stage(1, 64);
    CP_COMMIT();

    int stg = 0;
    for (int c = 0; c < nch; c++) {
        // pending groups here: chunks c, c+1 -> wait until <=1 pending
        CP_WAIT1();
        __syncthreads();   // single barrier per chunk: data ready + stage reuse

        // issue loads for chunk c+2 into stage (c+2)%3 (read in c-1, ordered
        // by the barrier above)
        if (c + 2 < nch) load_stage((stg + 2 == NSTAGE) ? 0 : ((stg + 2 > NSTAGE) ? 1 : stg + 2), (c + 2) << 6);
        CP_COMMIT();

        const unsigned aBase = sb + stg * STAGE_BYTES + OFF_A + aOff;
        const unsigned bBase = sb + stg * STAGE_BYTES + OFF_B + bOff;

        #pragma unroll
        for (int ks = 0; ks < 4; ks++) {
            const unsigned kk = (unsigned)(ks * 32);
            unsigned aa[2][4], bb[4][4];
            ldm_x4(aa[0], aBase + 0 * (16 * PITCH) + kk);
            ldm_x4(aa[1], aBase + 1 * (16 * PITCH) + kk);
            #pragma unroll
            for (int jn = 0; jn < 4; jn++)
                ldm_x4(bb[jn], bBase + jn * (16 * PITCH) + kk);
            #pragma unroll
            for (int im = 0; im < 2; im++)
                #pragma unroll
                for (int jn = 0; jn < 4; jn++) {
                    mma4h(acc[im][2 * jn],     aa[im], bb[jn] + 0);
                    mma4h(acc[im][2 * jn + 1], aa[im], bb[jn] + 2);
                }
        }
        stg = (stg + 1 == NSTAGE) ? 0 : stg + 1;
    }

    // ---- Epilogue ----
    const int r0 = bm + warp_m * 32 + (lane >> 2);
    const int c0 = bn + warp_n * 64 + (lane & 3) * 2;

    if (EPI == 0) {
        Cf += (size_t)z * cSlot;
        #pragma unroll
        for (int im = 0; im < 2; im++)
            #pragma unroll
            for (int j = 0; j < 8; j++) {
                const int row = r0 + im * 16;
                const int col = c0 + j * 8;
                const float s0 = rowScale ? rowScale[row] : alpha;
                const float s1 = rowScale ? rowScale[row + 8] : alpha;
                float2 v0 = make_float2(s0 * acc[im][j][0], s0 * acc[im][j][1]);
                float2 v1 = make_float2(s1 * acc[im][j][2], s1 * acc[im][j][3]);
                *reinterpret_cast<float2*>(&Cf[(size_t)row * N + col]) = v0;
                *reinterpret_cast<float2*>(&Cf[(size_t)(row + 8) * N + col]) = v1;
            }
    } else {
        const float* bias = (z == 0) ? bias0 : (z == 1) ? bias1 : bias2;
        Ch += (size_t)z * cSlot;
        #pragma unroll
        for (int im = 0; im < 2; im++)
            #pragma unroll
            for (int j = 0; j < 8; j++) {
                const int row = r0 + im * 16;
                const int col = c0 + j * 8;
                const float b0 = bias[col], b1 = bias[col + 1];
                #pragma unroll
                for (int h = 0; h < 2; h++) {
                    const int rw = row + h * 8;
                    __half2 hv;
                    hv.x = __float2half_rn(acc[im][j][h * 2 + 0] + b0);
                    hv.y = __float2half_rn(acc[im][j][h * 2 + 1] + b1);
                    *reinterpret_cast<__half2*>(&Ch[(size_t)rw * N + col]) = hv;
                }
            }
    }
}

// ---------------------------------------------------------------------------
// X fp32 -> fp16
// ---------------------------------------------------------------------------
__global__ __launch_bounds__(256) void xcast(
    const float* __restrict__ X, __half* __restrict__ Xh)
{
    const size_t i = ((size_t)blockIdx.x * 256 + threadIdx.x) * 4;
    float4 v = *reinterpret_cast<const float4*>(&X[i]);
    __half2 h0, h1;
    h0.x = __float2half_rn(v.x); h0.y = __float2half_rn(v.y);
    h1.x = __float2half_rn(v.z); h1.y = __float2half_rn(v.w);
    *reinterpret_cast<__half2*>(&Xh[i]) = h0;
    *reinterpret_cast<__half2*>(&Xh[i + 2]) = h1;
}

// ---------------------------------------------------------------------------
// W [K][N] fp32 -> W^T [n][k] fp16, slot z
// ---------------------------------------------------------------------------
__global__ void wtrans(const float* __restrict__ Wq, const float* __restrict__ Wk,
                       const float* __restrict__ Wv, __half* __restrict__ Th)
{
    __shared__ float tile[32][33];
    const int z = blockIdx.z;
    const float* W = (z == 0) ? Wq : (z == 1) ? Wk : Wv;
    const int n0 = blockIdx.x * 32, k0 = blockIdx.y * 32;
    const int tx = threadIdx.x, ty = threadIdx.y;
    #pragma unroll
    for (int i = 0; i < 32; i += 8)
        tile[ty + i][tx] = W[(size_t)(k0 + ty + i) * DIM + n0 + tx];
    __syncthreads();
    const size_t base = (size_t)z * DIM * DIM;
    #pragma unroll
    for (int i = 0; i < 32; i += 8)
        Th[base + (size_t)(n0 + ty + i) * DIM + k0 + tx] =
            __float2half_rn(tile[tx][ty + i]);
}

// ---------------------------------------------------------------------------
// V fp16 [SEQ][DIM] -> V^T fp16 [DIM][SEQ]
// ---------------------------------------------------------------------------
__global__ void vtrans(const __half* __restrict__ V, __half* __restrict__ Vt)
{
    __shared__ __half t[32][33];
    const int d0 = blockIdx.x * 32, s0 = blockIdx.y * 32;
    const int tx = threadIdx.x, ty = threadIdx.y;
    #pragma unroll
    for (int i = 0; i < 32; i += 8)
        t[ty + i][tx] = V[(size_t)(s0 + ty + i) * DIM + d0 + tx];
    __syncthreads();
    #pragma unroll
    for (int i = 0; i < 32; i += 8)
        Vt[(size_t)(d0 + ty + i) * SEQ + s0 + tx] = t[tx][ty + i];
}

// ---------------------------------------------------------------------------
// Row softmax (deferred normalization): Ph = fp16(exp(S - max)),
// rowinv = 1/rowsum (applied in PV epilogue). One block per row.
// ---------------------------------------------------------------------------
__global__ __launch_bounds__(256) void softmax_h(
    const float* __restrict__ S, __half* __restrict__ Ph,
    float* __restrict__ rowinv)
{
    const size_t rowoff = (size_t)blockIdx.x * SEQ;
    const float* p = S + rowoff;
    __shared__ float red[256];
    const int tid = threadIdx.x;

    float m = -INFINITY;
    #pragma unroll
    for (int t = 0; t < 4; t++) {
        float4 v = *reinterpret_cast<const float4*>(&p[tid * 4 + t * 1024]);
        m = fmaxf(m, fmaxf(fmaxf(v.x, v.y), fmaxf(v.z, v.w)));
    }
    red[tid] = m;
    __syncthreads();
    for (int s = 128; s > 0; s >>= 1) {
        if (tid < s) red[tid] = fmaxf(red[tid], red[tid + s]);
        __syncthreads();
    }
    m = red[0];
    __syncthreads();

    float sum = 0.0f;
    #pragma unroll
    for (int t = 0; t < 4; t++) {
        const int i = tid * 4 + t * 1024;
        float4 v = *reinterpret_cast<const float4*>(&p[i]);
        v.x = expf(v.x - m); v.y = expf(v.y - m);
        v.z = expf(v.z - m); v.w = expf(v.w - m);
        sum += v.x + v.y + v.z + v.w;
        __half2 h0, h1;
        h0.x = __float2half_rn(v.x); h0.y = __float2half_rn(v.y);
        h1.x = __float2half_rn(v.z); h1.y = __float2half_rn(v.w);
        *reinterpret_cast<__half2*>(&Ph[rowoff + i]) = h0;
        *reinterpret_cast<__half2*>(&Ph[rowoff + i + 2]) = h1;
    }
    red[tid] = sum;
    __syncthreads();
    for (int s = 128; s > 0; s >>= 1) {
        if (tid < s) red[tid] += red[tid + s];
        __syncthreads();
    }
    if (tid == 0) rowinv[blockIdx.x] = 1.0f / red[0];
}

// ---------------------------------------------------------------------------
// Launch — ordered so the ncu capture (launch #4) hits the big QK^T GEMM.
// ---------------------------------------------------------------------------
extern "C" void kernel_launch(void* const* d_in, const int* in_sizes, int n_in,
                              void* d_out, int out_size)
{
    const float* X  = (const float*)d_in[0];
    const float* Wq = (const float*)d_in[1];
    const float* bq = (const float*)d_in[2];
    const float* Wk = (const float*)d_in[3];
    const float* bk = (const float*)d_in[4];
    const float* Wv = (const float*)d_in[5];
    const float* bv = (const float*)d_in[6];
    float* out = (float*)d_out;

    __half *Xh, *Wth, *QKVh, *Vth, *Ph;
    float *S, *rowinv;
    cudaGetSymbolAddress((void**)&Xh, g_Xh);
    cudaGetSymbolAddress((void**)&Wth, g_Wth);
    cudaGetSymbolAddress((void**)&QKVh, g_QKVh);
    cudaGetSymbolAddress((void**)&Vth, g_Vth);
    cudaGetSymbolAddress((void**)&S, g_S);
    cudaGetSymbolAddress((void**)&Ph, g_Ph);
    cudaGetSymbolAddress((void**)&rowinv, g_rowinv);

    cudaFuncSetAttribute(h16_gemm<0>, cudaFuncAttributeMaxDynamicSharedMemorySize, SMEM_BYTES);
    cudaFuncSetAttribute(h16_gemm<1>, cudaFuncAttributeMaxDynamicSharedMemorySize, SMEM_BYTES);

    // 1) X -> fp16
    xcast<<<SEQ * DIM / 1024, 256>>>(X, Xh);
    // 2) W -> W^T fp16 (3 slots)
    wtrans<<<dim3(DIM / 32, DIM / 32, 3), dim3(32, 8)>>>(Wq, Wk, Wv, Wth);
    // 3) QKV projections (fused over z) + bias -> fp16
    h16_gemm<1><<<dim3(DIM / 128, SEQ / 128, 3), 256, SMEM_BYTES>>>(
        Xh, Wth, bq, bk, bv, nullptr,
        nullptr, QKVh,
        SEQ, DIM, DIM, 1.0f, (size_t)DIM * DIM, (size_t)SEQ * DIM);
    // 4) S = (Q @ K^T) / 32   <-- ncu capture target (launch #4)
    h16_gemm<0><<<dim3(SEQ / 128, SEQ / 128, 1), 256, SMEM_BYTES>>>(
        QKVh, QKVh + (size_t)SEQ * DIM,
        nullptr, nullptr, nullptr, nullptr,
        S, nullptr,
        SEQ, SEQ, DIM, 1.0f / 32.0f, 0, 0);
    // 5) V^T fp16
    vtrans<<<dim3(DIM / 32, SEQ / 32), dim3(32, 8)>>>(
        QKVh + 2 * (size_t)SEQ * DIM, Vth);
    // 6) softmax (deferred norm) -> P fp16 + rowinv
    softmax_h<<<SEQ, 256>>>(S, Ph, rowinv);
    // 7) out = (P @ V^T) * rowinv[row]
    h16_gemm<0><<<dim3(DIM / 128, SEQ / 128, 1), 256, SMEM_BYTES>>>(
        Ph, Vth,
        nullptr, nullptr, nullptr, rowinv,
        out, nullptr,
        SEQ, DIM, SEQ, 1.0f, 0, 0);
}